// round 2
// baseline (speedup 1.0000x reference)
#include <cuda_runtime.h>
#include <math.h>

// ---------------------------------------------------------------------------
// Fused MlpExtractor, round 2: packed fma.rn.f32x2 GEMM cores + MUFU tanh/exp.
// One CTA = 128 rows, 256 threads. Output: [action B*6 | vf B*128 | expout B*12]
// ---------------------------------------------------------------------------

static constexpr int ROWS = 128;
static constexpr int TPB  = 256;

static constexpr int SA_STRIDE = 132;
static constexpr int SL_STRIDE = 68;

static constexpr int SA_OFF   = 0;                          // 128*132
static constexpr int SW_OFF   = SA_OFF + 128 * SA_STRIDE;   // 128*128
static constexpr int SL_OFF   = SW_OFF + 128 * 128;         // 128*68
static constexpr int SG_OFF   = SL_OFF + 128 * SL_STRIDE;   // 256 gates
static constexpr int SACT_OFF = SG_OFF + 256;               // 128*12
static constexpr int SW2_OFF  = SACT_OFF + 128 * 12;        // 768 We2 + 12 be2 + pad
static constexpr int SGW_OFF  = SW2_OFF + 784;              // w_gate(124)+w_noise(124)+pad
static constexpr int SMEM_FLOATS = SGW_OFF + 256;
static constexpr int SMEM_BYTES  = SMEM_FLOATS * 4;

// ---- packed f32x2 helpers --------------------------------------------------
struct f2 {
    union { unsigned long long u; float2 v; };
};

__device__ __forceinline__ f2 dup2(float a) {
    f2 r;
    asm("mov.b64 %0, {%1, %1};" : "=l"(r.u) : "f"(a));
    return r;
}

__device__ __forceinline__ void fma2(f2& c, const f2& a, const f2& b) {
    asm("fma.rn.f32x2 %0, %1, %2, %0;" : "+l"(c.u) : "l"(a.u), "l"(b.u));
}

__device__ __forceinline__ float tanh_fast(float x) {
    // tanh(x) = 1 - 2/(exp(2x)+1); MUFU EX2 + RCP, err ~1e-6, saturates correctly
    float e = __expf(2.0f * x);
    return 1.0f - 2.0f * (1.0f / (e + 1.0f));
}

__device__ __forceinline__ float softplus_fast(float x) {
    return fmaxf(x, 0.f) + log1pf(__expf(-fabsf(x)));
}

// C[8 rows x 8 cols (4 f2 pairs)] += A[8xK] * B[Kx8], packed f32x2
template <int K, int AS, int BS>
__device__ __forceinline__ void gemm8x8p(const float* __restrict__ A,
                                         const float* __restrict__ Bm,
                                         int ty, int tx, f2 acc[8][4]) {
#pragma unroll 1
    for (int k = 0; k < K; k += 4) {
        float4 a4[8];
#pragma unroll
        for (int i = 0; i < 8; i++)
            a4[i] = *(const float4*)(A + (ty * 8 + i) * AS + k);
#pragma unroll
        for (int kk = 0; kk < 4; kk++) {
            const float2* bp = (const float2*)(Bm + (k + kk) * BS + tx * 8);
            f2 b0, b1, b2, b3;
            b0.v = bp[0]; b1.v = bp[1]; b2.v = bp[2]; b3.v = bp[3];
#pragma unroll
            for (int i = 0; i < 8; i++) {
                float a = (kk == 0) ? a4[i].x : (kk == 1) ? a4[i].y
                         : (kk == 2) ? a4[i].z : a4[i].w;
                f2 aa = dup2(a);
                fma2(acc[i][0], aa, b0);
                fma2(acc[i][1], aa, b1);
                fma2(acc[i][2], aa, b2);
                fma2(acc[i][3], aa, b3);
            }
        }
    }
}

// C[8 rows x 4 cols (2 f2 pairs)] += A[8xK] * B[Kx4], packed f32x2
template <int K, int AS, int BS>
__device__ __forceinline__ void gemm8x4p(const float* __restrict__ A,
                                         const float* __restrict__ Bm,
                                         int ty, int tx, f2 acc[8][2]) {
#pragma unroll 1
    for (int k = 0; k < K; k += 4) {
        float4 a4[8];
#pragma unroll
        for (int i = 0; i < 8; i++)
            a4[i] = *(const float4*)(A + (ty * 8 + i) * AS + k);
#pragma unroll
        for (int kk = 0; kk < 4; kk++) {
            const float2* bp = (const float2*)(Bm + (k + kk) * BS + tx * 4);
            f2 b0, b1;
            b0.v = bp[0]; b1.v = bp[1];
#pragma unroll
            for (int i = 0; i < 8; i++) {
                float a = (kk == 0) ? a4[i].x : (kk == 1) ? a4[i].y
                         : (kk == 2) ? a4[i].z : a4[i].w;
                f2 aa = dup2(a);
                fma2(acc[i][0], aa, b0);
                fma2(acc[i][1], aa, b1);
            }
        }
    }
}

__global__ void __launch_bounds__(TPB, 1) mlp_fused_kernel(
    const float* __restrict__ feat,   const float* __restrict__ noise,
    const float* __restrict__ Ws0,    const float* __restrict__ bs0,
    const float* __restrict__ Ws1,    const float* __restrict__ bs1,
    const float* __restrict__ Wv,     const float* __restrict__ bv,
    const float* __restrict__ w_gate, const float* __restrict__ w_noise,
    const float* __restrict__ We1,    const float* __restrict__ be1,
    const float* __restrict__ We2,    const float* __restrict__ be2,
    float* __restrict__ out_action, float* __restrict__ out_vf,
    float* __restrict__ out_expout)
{
    extern __shared__ float sm[];
    float* sA   = sm + SA_OFF;    // feat -> h -> eh   [128][132]
    float* sW   = sm + SW_OFF;    // staged weights
    float* sL   = sm + SL_OFF;    // latent            [128][68]
    float* sG   = sm + SG_OFF;    // gates             [128][2]
    float* sAct = sm + SACT_OFF;  // gate*expout       [128][12]
    float* sW2  = sm + SW2_OFF;   // We2(768)+be2(12)
    float* sGW  = sm + SGW_OFF;   // w_gate(124)+w_noise(124)

    const int tid  = threadIdx.x;
    const int row0 = blockIdx.x * ROWS;
    const int tx = tid & 15, ty = tid >> 4;

    // ---- stage features, Ws0, We2/be2, gating weights ----
    for (int i = tid; i < ROWS * 32; i += TPB) {
        int r = i >> 5, c4 = (i & 31) << 2;
        *(float4*)&sA[r * SA_STRIDE + c4] =
            *(const float4*)&feat[(size_t)(row0 + r) * 128 + c4];
    }
    for (int i = tid; i < 128 * 32; i += TPB) {
        int r = i >> 5, c4 = (i & 31) << 2;
        *(float4*)&sW[r * 128 + c4] = *(const float4*)&Ws0[r * 128 + c4];
    }
    for (int i = tid; i < 768; i += TPB) sW2[i] = We2[i];
    if (tid < 12)  sW2[768 + tid] = be2[tid];
    if (tid >= 32 && tid < 32 + 124) sGW[tid - 32] = w_gate[tid - 32];
    if (tid >= 160 && tid < 160 + 124) sGW[128 + tid - 160] = w_noise[tid - 160];
    __syncthreads();

    // ================= Phase A: h = tanh(feat @ Ws0 + bs0) =================
    f2 acc[8][4];
#pragma unroll
    for (int i = 0; i < 8; i++)
#pragma unroll
        for (int j = 0; j < 4; j++) acc[i][j].u = 0ull;
    gemm8x8p<128, SA_STRIDE, 128>(sA, sW, ty, tx, acc);
    __syncthreads();
    {
        float bb[8];
#pragma unroll
        for (int j = 0; j < 8; j++) bb[j] = bs0[tx * 8 + j];
#pragma unroll
        for (int i = 0; i < 8; i++)
#pragma unroll
            for (int j = 0; j < 4; j++) {
                sA[(ty * 8 + i) * SA_STRIDE + tx * 8 + 2 * j]     =
                    tanh_fast(acc[i][j].v.x + bb[2 * j]);
                sA[(ty * 8 + i) * SA_STRIDE + tx * 8 + 2 * j + 1] =
                    tanh_fast(acc[i][j].v.y + bb[2 * j + 1]);
            }
    }
    // stage Ws1 (padded to [128][64]) into sW
    for (int i = tid; i < 128 * 64; i += TPB) {
        int k = i >> 6, c = i & 63;
        sW[i] = (c < 62) ? Ws1[k * 62 + c] : 0.f;
    }
    __syncthreads();

    // ================= Phase B: latent = tanh(h @ Ws1 + bs1) ===============
    f2 accB[8][2];
#pragma unroll
    for (int i = 0; i < 8; i++)
#pragma unroll
        for (int j = 0; j < 2; j++) accB[i][j].u = 0ull;
    gemm8x4p<128, SA_STRIDE, 64>(sA, sW, ty, tx, accB);
    __syncthreads();
    {
        float bb[4];
#pragma unroll
        for (int j = 0; j < 4; j++) {
            int c = tx * 4 + j;
            bb[j] = (c < 62) ? bs1[c] : 0.f;
        }
#pragma unroll
        for (int i = 0; i < 8; i++) {
            sL[(ty * 8 + i) * SL_STRIDE + tx * 4 + 0] = tanh_fast(accB[i][0].v.x + bb[0]);
            sL[(ty * 8 + i) * SL_STRIDE + tx * 4 + 1] = tanh_fast(accB[i][0].v.y + bb[1]);
            sL[(ty * 8 + i) * SL_STRIDE + tx * 4 + 2] = tanh_fast(accB[i][1].v.x + bb[2]);
            sL[(ty * 8 + i) * SL_STRIDE + tx * 4 + 3] = tanh_fast(accB[i][1].v.y + bb[3]);
        }
    }
    // stage Wv (padded to [64][128]) into sW
    for (int i = tid; i < 64 * 32; i += TPB) {
        int k = i >> 5, c4 = (i & 31) << 2;
        float4 v = make_float4(0.f, 0.f, 0.f, 0.f);
        if (k < 62) v = *(const float4*)&Wv[k * 128 + c4];
        *(float4*)&sW[k * 128 + c4] = v;
    }
    __syncthreads();

    // ============ Phase D: noisy gating (one thread per row) ===============
    if (tid < 128) {
        f2 c; c.u = 0ull;
        f2 n; n.u = 0ull;
        const float* lrow = &sL[tid * SL_STRIDE];
        const float2* wg = (const float2*)sGW;          // [62] pairs
        const float2* wn = (const float2*)(sGW + 128);  // [62] pairs
#pragma unroll 2
        for (int k = 0; k < 62; k++) {
            f2 l = dup2(lrow[k]);
            f2 g; g.v = wg[k];
            f2 m; m.v = wn[k];
            fma2(c, l, g);
            fma2(n, l, m);
        }
        float s0 = softplus_fast(n.v.x) + 1e-2f;
        float s1 = softplus_fast(n.v.y) + 1e-2f;
        float z0 = fmaf(noise[(size_t)(row0 + tid) * 2 + 0], s0, c.v.x);
        float z1 = fmaf(noise[(size_t)(row0 + tid) * 2 + 1], s1, c.v.y);
        float mx = fmaxf(z0, z1);
        float e0 = __expf(z0 - mx), e1 = __expf(z1 - mx);
        float inv = 1.f / (e0 + e1);
        sG[2 * tid + 0] = e0 * inv;
        sG[2 * tid + 1] = e1 * inv;
    }

    // ============ Phase C: latent_vf = tanh(latent @ Wv + bv) ==============
#pragma unroll
    for (int i = 0; i < 8; i++)
#pragma unroll
        for (int j = 0; j < 4; j++) acc[i][j].u = 0ull;
    gemm8x8p<64, SL_STRIDE, 128>(sL, sW, ty, tx, acc);
    __syncthreads();
    {
        float bb[8];
#pragma unroll
        for (int j = 0; j < 8; j++) bb[j] = bv[tx * 8 + j];
#pragma unroll
        for (int i = 0; i < 8; i++) {
            float4 v0, v1;
            v0.x = tanh_fast(acc[i][0].v.x + bb[0]);
            v0.y = tanh_fast(acc[i][0].v.y + bb[1]);
            v0.z = tanh_fast(acc[i][1].v.x + bb[2]);
            v0.w = tanh_fast(acc[i][1].v.y + bb[3]);
            v1.x = tanh_fast(acc[i][2].v.x + bb[4]);
            v1.y = tanh_fast(acc[i][2].v.y + bb[5]);
            v1.z = tanh_fast(acc[i][3].v.x + bb[6]);
            v1.w = tanh_fast(acc[i][3].v.y + bb[7]);
            size_t g = (size_t)(row0 + ty * 8 + i) * 128 + tx * 8;
            *(float4*)&out_vf[g]     = v0;
            *(float4*)&out_vf[g + 4] = v1;
        }
    }
    // stage We1 concat (padded to [64][128], cols = e*64+hid) into sW
    for (int i = tid; i < 64 * 128; i += TPB) {
        int k = i >> 7, c = i & 127;
        int e = c >> 6, hid = c & 63;
        sW[i] = (k < 62) ? We1[((e * 62 + k) << 6) + hid] : 0.f;
    }
    __syncthreads();

    // ========= Phase E: eh = relu(latent @ We1 + be1)  [128][2*64] =========
#pragma unroll
    for (int i = 0; i < 8; i++)
#pragma unroll
        for (int j = 0; j < 4; j++) acc[i][j].u = 0ull;
    gemm8x8p<64, SL_STRIDE, 128>(sL, sW, ty, tx, acc);
    {
        float bb[8];
#pragma unroll
        for (int j = 0; j < 8; j++) bb[j] = be1[tx * 8 + j];
#pragma unroll
        for (int i = 0; i < 8; i++)
#pragma unroll
            for (int j = 0; j < 4; j++) {
                sA[(ty * 8 + i) * SA_STRIDE + tx * 8 + 2 * j] =
                    fmaxf(acc[i][j].v.x + bb[2 * j], 0.f);
                sA[(ty * 8 + i) * SA_STRIDE + tx * 8 + 2 * j + 1] =
                    fmaxf(acc[i][j].v.y + bb[2 * j + 1], 0.f);
            }
    }
    __syncthreads();

    // ====== Phase F: expout softmax + gated combine (thread=(row,e)) =======
    {
        int row = tid >> 1, e = tid & 1;
        f2 lg[3];
#pragma unroll
        for (int o = 0; o < 3; o++) lg[o].v = *(const float2*)&sW2[768 + e * 6 + 2 * o];
        const float*  ehrow = &sA[row * SA_STRIDE + e * 64];
        const float2* w2    = (const float2*)&sW2[e * 64 * 6];
#pragma unroll 8
        for (int h = 0; h < 64; h++) {
            f2 x = dup2(ehrow[h]);
            f2 w0, w1, w2v;
            w0.v = w2[h * 3 + 0]; w1.v = w2[h * 3 + 1]; w2v.v = w2[h * 3 + 2];
            fma2(lg[0], x, w0);
            fma2(lg[1], x, w1);
            fma2(lg[2], x, w2v);
        }
        float lgs[6] = {lg[0].v.x, lg[0].v.y, lg[1].v.x, lg[1].v.y, lg[2].v.x, lg[2].v.y};
        float m = lgs[0];
#pragma unroll
        for (int o = 1; o < 6; o++) m = fmaxf(m, lgs[o]);
        float p[6], s = 0.f;
#pragma unroll
        for (int o = 0; o < 6; o++) { p[o] = __expf(lgs[o] - m); s += p[o]; }
        float inv = 1.f / s;
        float g = sG[tid];
        size_t gbase = ((size_t)(row0 + row) * 2 + e) * 6;
#pragma unroll
        for (int o = 0; o < 6; o++) {
            float po = p[o] * inv;
            out_expout[gbase + o] = po;
            sAct[tid * 6 + o] = g * po;
        }
    }
    __syncthreads();
    if (tid < 128) {
        size_t gbase = (size_t)(row0 + tid) * 6;
#pragma unroll
        for (int o = 0; o < 6; o++)
            out_action[gbase + o] = sAct[tid * 12 + o] + sAct[tid * 12 + 6 + o];
    }
}

extern "C" void kernel_launch(void* const* d_in, const int* in_sizes, int n_in,
                              void* d_out, int out_size) {
    const float* feat    = (const float*)d_in[0];
    const float* noise   = (const float*)d_in[1];
    const float* Ws0     = (const float*)d_in[2];
    const float* bs0     = (const float*)d_in[3];
    const float* Ws1     = (const float*)d_in[4];
    const float* bs1     = (const float*)d_in[5];
    const float* Wv      = (const float*)d_in[6];
    const float* bv      = (const float*)d_in[7];
    const float* w_gate  = (const float*)d_in[8];
    const float* w_noise = (const float*)d_in[9];
    const float* We1     = (const float*)d_in[10];
    const float* be1     = (const float*)d_in[11];
    const float* We2     = (const float*)d_in[12];
    const float* be2     = (const float*)d_in[13];

    const int B = in_sizes[0] / 128;

    float* out        = (float*)d_out;
    float* out_action = out;                       // [B,6]
    float* out_vf     = out + (size_t)B * 6;       // [B,128]
    float* out_expout = out + (size_t)B * 134;     // [B,2,6]

    cudaFuncSetAttribute(mlp_fused_kernel,
                         cudaFuncAttributeMaxDynamicSharedMemorySize, SMEM_BYTES);

    mlp_fused_kernel<<<B / ROWS, TPB, SMEM_BYTES>>>(
        feat, noise, Ws0, bs0, Ws1, bs1, Wv, bv, w_gate, w_noise,
        We1, be1, We2, be2, out_action, out_vf, out_expout);
}

// round 3
// speedup vs baseline: 1.1185x; 1.1185x over previous
#include <cuda_runtime.h>
#include <math.h>

// ---------------------------------------------------------------------------
// Fused MlpExtractor, round 3: tf32 mma.sync (m16n8k8) for all 4 big GEMMs.
// One CTA = 128 rows, 256 threads (8 warps x 16 rows).
// Output: [action B*6 | vf B*128 | expout B*12] fp32.
// ---------------------------------------------------------------------------

static constexpr int ROWS = 128;
static constexpr int TPB  = 256;

static constexpr int SA_S = 132;   // activations stride (feat/h/eh)
static constexpr int SW_S = 132;   // wide weights stride
static constexpr int SL_S = 68;    // latent stride
static constexpr int SW1_S = 68;   // Ws1 stride

static constexpr int SA_OFF   = 0;                         // 128*132 = 16896
static constexpr int SW_OFF   = SA_OFF + 128 * SA_S;       // 128*132 = 16896
static constexpr int SL_OFF   = SW_OFF + 128 * SW_S;       // 128*68  = 8704
static constexpr int SG_OFF   = SL_OFF + 128 * SL_S;       // 256
static constexpr int SACT_OFF = SG_OFF + 256;              // 1536
static constexpr int SW2_OFF  = SACT_OFF + 128 * 12;       // 784
static constexpr int SGW_OFF  = SW2_OFF + 784;             // 256
static constexpr int SMEM_FLOATS = SGW_OFF + 256;
static constexpr int SMEM_BYTES  = SMEM_FLOATS * 4;        // ~181 KB

// ---- helpers ----------------------------------------------------------------
__device__ __forceinline__ unsigned f2tf_u(float x) {
    unsigned u;
    asm("cvt.rna.tf32.f32 %0, %1;" : "=r"(u) : "f"(x));
    return u;
}
__device__ __forceinline__ float tf(float x) { return __uint_as_float(f2tf_u(x)); }

__device__ __forceinline__ float tanh_fast(float x) {
    float e = __expf(2.0f * x);
    return 1.0f - 2.0f * (1.0f / (e + 1.0f));
}
__device__ __forceinline__ float softplus_fast(float x) {
    return fmaxf(x, 0.f) + log1pf(__expf(-fabsf(x)));
}

struct f2 { union { unsigned long long u; float2 v; }; };
__device__ __forceinline__ f2 dup2(float a) {
    f2 r; asm("mov.b64 %0, {%1, %1};" : "=l"(r.u) : "f"(a)); return r;
}
__device__ __forceinline__ void fma2(f2& c, const f2& a, const f2& b) {
    asm("fma.rn.f32x2 %0, %1, %2, %0;" : "+l"(c.u) : "l"(a.u), "l"(b.u));
}

__device__ __forceinline__ void mma8(float d[4], unsigned a0, unsigned a1,
                                     unsigned a2, unsigned a3,
                                     unsigned b0, unsigned b1) {
    asm("mma.sync.aligned.m16n8k8.row.col.f32.tf32.tf32.f32 "
        "{%0,%1,%2,%3},{%4,%5,%6,%7},{%8,%9},{%0,%1,%2,%3};"
        : "+f"(d[0]), "+f"(d[1]), "+f"(d[2]), "+f"(d[3])
        : "r"(a0), "r"(a1), "r"(a2), "r"(a3), "r"(b0), "r"(b1));
}

// Warp computes [16 rows x NT*8 cols] over K = KC*8. Operands are tf32-in-f32
// bit patterns already staged in smem. Conflict-free for AS/BS in {132, 68}.
template <int KC, int NT, int AS, int BS>
__device__ __forceinline__ void mma_gemm(const float* __restrict__ A,
                                         const float* __restrict__ B,
                                         int wrow, int lane, float (&acc)[NT][4]) {
    const int r = lane >> 2, c = lane & 3;
    const float* ap = A + (wrow + r) * AS + c;
    const float* bp = B + c * BS + r;
#pragma unroll 1
    for (int kc = 0; kc < KC; kc++) {
        unsigned a0 = __float_as_uint(ap[kc * 8]);
        unsigned a1 = __float_as_uint(ap[kc * 8 + 8 * AS]);
        unsigned a2 = __float_as_uint(ap[kc * 8 + 4]);
        unsigned a3 = __float_as_uint(ap[kc * 8 + 8 * AS + 4]);
        const float* bk = bp + kc * 8 * BS;
#pragma unroll
        for (int nt = 0; nt < NT; nt++) {
            unsigned b0 = __float_as_uint(bk[nt * 8]);
            unsigned b1 = __float_as_uint(bk[nt * 8 + 4 * BS]);
            mma8(acc[nt], a0, a1, a2, a3, b0, b1);
        }
    }
}

template <int NT> __device__ __forceinline__ void zacc(float (&acc)[NT][4]) {
#pragma unroll
    for (int i = 0; i < NT; i++)
#pragma unroll
        for (int j = 0; j < 4; j++) acc[i][j] = 0.f;
}

__global__ void __launch_bounds__(TPB, 1) mlp_fused_kernel(
    const float* __restrict__ feat,   const float* __restrict__ noise,
    const float* __restrict__ Ws0,    const float* __restrict__ bs0,
    const float* __restrict__ Ws1,    const float* __restrict__ bs1,
    const float* __restrict__ Wv,     const float* __restrict__ bv,
    const float* __restrict__ w_gate, const float* __restrict__ w_noise,
    const float* __restrict__ We1,    const float* __restrict__ be1,
    const float* __restrict__ We2,    const float* __restrict__ be2,
    float* __restrict__ out_action, float* __restrict__ out_vf,
    float* __restrict__ out_expout)
{
    extern __shared__ float sm[];
    float* sA   = sm + SA_OFF;    // feat -> h -> eh   [128][132] (tf32 for feat/h)
    float* sW   = sm + SW_OFF;    // staged weights (tf32)
    float* sL   = sm + SL_OFF;    // latent (tf32)     [128][68]
    float* sG   = sm + SG_OFF;    // gates             [128][2]
    float* sAct = sm + SACT_OFF;  // gate*expout       [128][12]
    float* sW2  = sm + SW2_OFF;   // We2(768)+be2(12)
    float* sGW  = sm + SGW_OFF;   // w_gate(124)+w_noise(124)

    const int tid  = threadIdx.x;
    const int lane = tid & 31;
    const int wrow = (tid >> 5) * 16;           // warp's row base
    const int r = lane >> 2, c = lane & 3;
    const int row0 = blockIdx.x * ROWS;

    // ---- stage: feat (tf32), Ws0 (tf32), We2/be2, gating weights ----
    for (int i = tid; i < ROWS * 32; i += TPB) {
        int rr = i >> 5, c4 = (i & 31) << 2;
        float4 v = *(const float4*)&feat[(size_t)(row0 + rr) * 128 + c4];
        v.x = tf(v.x); v.y = tf(v.y); v.z = tf(v.z); v.w = tf(v.w);
        *(float4*)&sA[rr * SA_S + c4] = v;
    }
    for (int i = tid; i < 128 * 32; i += TPB) {
        int rr = i >> 5, c4 = (i & 31) << 2;
        float4 v = *(const float4*)&Ws0[rr * 128 + c4];
        v.x = tf(v.x); v.y = tf(v.y); v.z = tf(v.z); v.w = tf(v.w);
        *(float4*)&sW[rr * SW_S + c4] = v;
    }
    for (int i = tid; i < 768; i += TPB) sW2[i] = We2[i];
    if (tid < 12)  sW2[768 + tid] = be2[tid];
    if (tid >= 32 && tid < 32 + 124)  sGW[tid - 32] = w_gate[tid - 32];
    if (tid >= 160 && tid < 160 + 124) sGW[128 + tid - 160] = w_noise[tid - 160];
    __syncthreads();

    // ================= Phase A: h = tanh(feat @ Ws0 + bs0), N=128 ==========
    {
        float acc[16][4];
        zacc(acc);
        mma_gemm<16, 16, SA_S, SW_S>(sA, sW, wrow, lane, acc);
        __syncthreads();
#pragma unroll
        for (int nt = 0; nt < 16; nt++) {
            int col = nt * 8 + 2 * c;
            float2 bb = *(const float2*)&bs0[col];
            float2 lo, hi;
            lo.x = tf(tanh_fast(acc[nt][0] + bb.x));
            lo.y = tf(tanh_fast(acc[nt][1] + bb.y));
            hi.x = tf(tanh_fast(acc[nt][2] + bb.x));
            hi.y = tf(tanh_fast(acc[nt][3] + bb.y));
            *(float2*)&sA[(wrow + r) * SA_S + col]     = lo;
            *(float2*)&sA[(wrow + r + 8) * SA_S + col] = hi;
        }
        // stage Ws1 (tf32, padded [128][68]) into sW
        for (int i = tid; i < 128 * SW1_S; i += TPB) {
            int k = i / SW1_S, cc = i - k * SW1_S;
            sW[i] = (cc < 62) ? tf(Ws1[k * 62 + cc]) : 0.f;
        }
        __syncthreads();
    }

    // ================= Phase B: latent = tanh(h @ Ws1 + bs1), N=64 =========
    {
        float acc[8][4];
        zacc(acc);
        mma_gemm<16, 8, SA_S, SW1_S>(sA, sW, wrow, lane, acc);
        __syncthreads();
#pragma unroll
        for (int nt = 0; nt < 8; nt++) {
            int col = nt * 8 + 2 * c;
            float bx = (col < 62)     ? bs1[col]     : 0.f;
            float by = (col + 1 < 62) ? bs1[col + 1] : 0.f;
            float2 lo, hi;
            lo.x = tf(tanh_fast(acc[nt][0] + bx));
            lo.y = tf(tanh_fast(acc[nt][1] + by));
            hi.x = tf(tanh_fast(acc[nt][2] + bx));
            hi.y = tf(tanh_fast(acc[nt][3] + by));
            *(float2*)&sL[(wrow + r) * SL_S + col]     = lo;
            *(float2*)&sL[(wrow + r + 8) * SL_S + col] = hi;
        }
        // stage Wv (tf32, padded [64][132]) into sW
        for (int i = tid; i < 64 * 128; i += TPB) {
            int k = i >> 7, cc = i & 127;
            sW[k * SW_S + cc] = (k < 62) ? tf(Wv[k * 128 + cc]) : 0.f;
        }
        __syncthreads();
    }

    // ============ Phase D: noisy gating (one thread per row) ===============
    if (tid < 128) {
        f2 cg; cg.u = 0ull;
        f2 cn; cn.u = 0ull;
        const float* lrow = &sL[tid * SL_S];
        const float2* wg = (const float2*)sGW;
        const float2* wn = (const float2*)(sGW + 128);
#pragma unroll 2
        for (int k = 0; k < 62; k++) {
            f2 l = dup2(lrow[k]);
            f2 g; g.v = wg[k];
            f2 m; m.v = wn[k];
            fma2(cg, l, g);
            fma2(cn, l, m);
        }
        float s0 = softplus_fast(cn.v.x) + 1e-2f;
        float s1 = softplus_fast(cn.v.y) + 1e-2f;
        float z0 = fmaf(noise[(size_t)(row0 + tid) * 2 + 0], s0, cg.v.x);
        float z1 = fmaf(noise[(size_t)(row0 + tid) * 2 + 1], s1, cg.v.y);
        float mx = fmaxf(z0, z1);
        float e0 = __expf(z0 - mx), e1 = __expf(z1 - mx);
        float inv = 1.f / (e0 + e1);
        sG[2 * tid + 0] = e0 * inv;
        sG[2 * tid + 1] = e1 * inv;
    }

    // ============ Phase C: latent_vf = tanh(latent @ Wv + bv), N=128 =======
    {
        float acc[16][4];
        zacc(acc);
        mma_gemm<8, 16, SL_S, SW_S>(sL, sW, wrow, lane, acc);
        __syncthreads();
#pragma unroll
        for (int nt = 0; nt < 16; nt++) {
            int col = nt * 8 + 2 * c;
            float2 bb = *(const float2*)&bv[col];
            float2 lo, hi;
            lo.x = tanh_fast(acc[nt][0] + bb.x);
            lo.y = tanh_fast(acc[nt][1] + bb.y);
            hi.x = tanh_fast(acc[nt][2] + bb.x);
            hi.y = tanh_fast(acc[nt][3] + bb.y);
            *(float2*)&out_vf[(size_t)(row0 + wrow + r) * 128 + col]     = lo;
            *(float2*)&out_vf[(size_t)(row0 + wrow + r + 8) * 128 + col] = hi;
        }
        // stage We1 concat (tf32, padded [64][132], cols = e*64+hid) into sW
        for (int i = tid; i < 64 * 128; i += TPB) {
            int k = i >> 7, cc = i & 127;
            int e = cc >> 6, hid = cc & 63;
            sW[k * SW_S + cc] = (k < 62) ? tf(We1[((e * 62 + k) << 6) + hid]) : 0.f;
        }
        __syncthreads();
    }

    // ========= Phase E: eh = relu(latent @ We1 + be1), N=128 ===============
    {
        float acc[16][4];
        zacc(acc);
        mma_gemm<8, 16, SL_S, SW_S>(sL, sW, wrow, lane, acc);
#pragma unroll
        for (int nt = 0; nt < 16; nt++) {
            int col = nt * 8 + 2 * c;
            float2 bb = *(const float2*)&be1[col];
            float2 lo, hi;
            lo.x = fmaxf(acc[nt][0] + bb.x, 0.f);
            lo.y = fmaxf(acc[nt][1] + bb.y, 0.f);
            hi.x = fmaxf(acc[nt][2] + bb.x, 0.f);
            hi.y = fmaxf(acc[nt][3] + bb.y, 0.f);
            *(float2*)&sA[(wrow + r) * SA_S + col]     = lo;
            *(float2*)&sA[(wrow + r + 8) * SA_S + col] = hi;
        }
        __syncthreads();
    }

    // ====== Phase F: expert softmax + gated combine (thread=(row,e)) =======
    {
        int row = tid >> 1, e = tid & 1;
        f2 lg[3];
#pragma unroll
        for (int o = 0; o < 3; o++) lg[o].v = *(const float2*)&sW2[768 + e * 6 + 2 * o];
        const float*  ehrow = &sA[row * SA_S + e * 64];
        const float2* w2    = (const float2*)&sW2[e * 64 * 6];
#pragma unroll 8
        for (int h = 0; h < 64; h++) {
            f2 x = dup2(ehrow[h]);
            f2 w0, w1, w2v;
            w0.v = w2[h * 3 + 0]; w1.v = w2[h * 3 + 1]; w2v.v = w2[h * 3 + 2];
            fma2(lg[0], x, w0);
            fma2(lg[1], x, w1);
            fma2(lg[2], x, w2v);
        }
        float lgs[6] = {lg[0].v.x, lg[0].v.y, lg[1].v.x, lg[1].v.y, lg[2].v.x, lg[2].v.y};
        float m = lgs[0];
#pragma unroll
        for (int o = 1; o < 6; o++) m = fmaxf(m, lgs[o]);
        float p[6], s = 0.f;
#pragma unroll
        for (int o = 0; o < 6; o++) { p[o] = __expf(lgs[o] - m); s += p[o]; }
        float inv = 1.f / s;
        float g = sG[tid];
        size_t gbase = ((size_t)(row0 + row) * 2 + e) * 6;
#pragma unroll
        for (int o = 0; o < 6; o++) {
            float po = p[o] * inv;
            out_expout[gbase + o] = po;
            sAct[tid * 6 + o] = g * po;
        }
    }
    __syncthreads();
    if (tid < 128) {
        size_t gbase = (size_t)(row0 + tid) * 6;
#pragma unroll
        for (int o = 0; o < 6; o++)
            out_action[gbase + o] = sAct[tid * 12 + o] + sAct[tid * 12 + 6 + o];
    }
}

extern "C" void kernel_launch(void* const* d_in, const int* in_sizes, int n_in,
                              void* d_out, int out_size) {
    const float* feat    = (const float*)d_in[0];
    const float* noise   = (const float*)d_in[1];
    const float* Ws0     = (const float*)d_in[2];
    const float* bs0     = (const float*)d_in[3];
    const float* Ws1     = (const float*)d_in[4];
    const float* bs1     = (const float*)d_in[5];
    const float* Wv      = (const float*)d_in[6];
    const float* bv      = (const float*)d_in[7];
    const float* w_gate  = (const float*)d_in[8];
    const float* w_noise = (const float*)d_in[9];
    const float* We1     = (const float*)d_in[10];
    const float* be1     = (const float*)d_in[11];
    const float* We2     = (const float*)d_in[12];
    const float* be2     = (const float*)d_in[13];

    const int B = in_sizes[0] / 128;

    float* out        = (float*)d_out;
    float* out_action = out;                       // [B,6]
    float* out_vf     = out + (size_t)B * 6;       // [B,128]
    float* out_expout = out + (size_t)B * 134;     // [B,2,6]

    cudaFuncSetAttribute(mlp_fused_kernel,
                         cudaFuncAttributeMaxDynamicSharedMemorySize, SMEM_BYTES);

    mlp_fused_kernel<<<B / ROWS, TPB, SMEM_BYTES>>>(
        feat, noise, Ws0, bs0, Ws1, bs1, Wv, bv, w_gate, w_noise,
        We1, be1, We2, be2, out_action, out_vf, out_expout);
}

// round 5
// speedup vs baseline: 2.5196x; 2.2528x over previous
#include <cuda_runtime.h>
#include <math.h>

// ---------------------------------------------------------------------------
// Round 5: R4 occupancy design with the fragment-conversion fix (no d1<->d2
// swap; frag_to_a maps the m16n8 output fragment directly to the tf32 A frag).
// Activations register-resident, feat A-frags from gmem, gating via MMA.
// smem 80KB => 2 CTAs/SM. tf32 m16n8k8 everywhere.
// Output: [action B*6 | vf B*128 | expout B*12] fp32.
// ---------------------------------------------------------------------------

static constexpr int ROWS = 128;
static constexpr int TPB  = 256;

static constexpr int SW_S  = 136;  // weight stage stride (k-major)
static constexpr int SW1_S = 72;   // Ws1 stride
static constexpr int SEH_S = 132;  // eh stride (phase F scratch)

static constexpr int SW_OFF   = 0;                     // 128*136 = 17408
static constexpr int SGB_OFF  = SW_OFF + 128 * SW_S;   // 64*8 = 512
static constexpr int SG_OFF   = SGB_OFF + 512;         // 256
static constexpr int SACT_OFF = SG_OFF + 256;          // 128*12 = 1536
static constexpr int SW2_OFF  = SACT_OFF + 1536;       // 784
static constexpr int SMEM_FLOATS = SW2_OFF + 784;      // 20496
static constexpr int SMEM_BYTES  = SMEM_FLOATS * 4;    // 81984 B

// ---- helpers ---------------------------------------------------------------
__device__ __forceinline__ unsigned f2tf_u(float x) {
    unsigned u; asm("cvt.rna.tf32.f32 %0, %1;" : "=r"(u) : "f"(x)); return u;
}
__device__ __forceinline__ float tf(float x) { return __uint_as_float(f2tf_u(x)); }

__device__ __forceinline__ float tanh_fast(float x) {
    float e = __expf(2.0f * x);
    return 1.0f - 2.0f * (1.0f / (e + 1.0f));
}
__device__ __forceinline__ float softplus_fast(float x) {
    return fmaxf(x, 0.f) + log1pf(__expf(-fabsf(x)));
}

struct f2 { union { unsigned long long u; float2 v; }; };
__device__ __forceinline__ f2 dup2(float a) {
    f2 r; asm("mov.b64 %0, {%1, %1};" : "=l"(r.u) : "f"(a)); return r;
}
__device__ __forceinline__ void fma2(f2& c, const f2& a, const f2& b) {
    asm("fma.rn.f32x2 %0, %1, %2, %0;" : "+l"(c.u) : "l"(a.u), "l"(b.u));
}

__device__ __forceinline__ void mma8(float d[4], unsigned a0, unsigned a1,
                                     unsigned a2, unsigned a3,
                                     unsigned b0, unsigned b1) {
    asm("mma.sync.aligned.m16n8k8.row.col.f32.tf32.tf32.f32 "
        "{%0,%1,%2,%3},{%4,%5,%6,%7},{%8,%9},{%0,%1,%2,%3};"
        : "+f"(d[0]), "+f"(d[1]), "+f"(d[2]), "+f"(d[3])
        : "r"(a0), "r"(a1), "r"(a2), "r"(a3), "r"(b0), "r"(b1));
}

// Convert an m16n8 OUTPUT fragment (d0=(r,2c), d1=(r,2c+1), d2=(r+8,2c),
// d3=(r+8,2c+1)) into the tf32 A fragment (a0=(r,c), a1=(r+8,c),
// a2=(r,c+4), a3=(r+8,c+4)) for k-chunk == this n-tile. In place.
__device__ __forceinline__ void frag_to_a(float (&d)[4], int lane) {
    int base = lane & ~3;                 // 4*r
    int src  = base | ((lane & 3) >> 1);  // holder of cols {2(c>>1), 2(c>>1)+1}
    float v0 = __shfl_sync(0xffffffffu, d[0], src);
    float v1 = __shfl_sync(0xffffffffu, d[1], src);
    float v2 = __shfl_sync(0xffffffffu, d[2], src);
    float v3 = __shfl_sync(0xffffffffu, d[3], src);
    float w0 = __shfl_sync(0xffffffffu, d[0], src + 2);
    float w1 = __shfl_sync(0xffffffffu, d[1], src + 2);
    float w2 = __shfl_sync(0xffffffffu, d[2], src + 2);
    float w3 = __shfl_sync(0xffffffffu, d[3], src + 2);
    bool odd = lane & 1;
    d[0] = odd ? v1 : v0;  // (r,   c)
    d[1] = odd ? v3 : v2;  // (r+8, c)
    d[2] = odd ? w1 : w0;  // (r,   c+4)
    d[3] = odd ? w3 : w2;  // (r+8, c+4)
}

// acc[NT] += A(frags) * B_panel(sW, stride BS), K = KC*8
template <int KC, int NT, int BS>
__device__ __forceinline__ void mma_panel(const float* __restrict__ sWp,
                                          const float (&a)[KC][4],
                                          float (&acc)[NT][4], int lane) {
    const int r = lane >> 2, c = lane & 3;
    const float* bw = sWp + c * BS + r;
#pragma unroll
    for (int kc = 0; kc < KC; kc++) {
        unsigned a0 = __float_as_uint(a[kc][0]);
        unsigned a1 = __float_as_uint(a[kc][1]);
        unsigned a2 = __float_as_uint(a[kc][2]);
        unsigned a3 = __float_as_uint(a[kc][3]);
        const float* bk = bw + kc * 8 * BS;
#pragma unroll
        for (int nt = 0; nt < NT; nt++) {
            unsigned b0 = __float_as_uint(bk[nt * 8]);
            unsigned b1 = __float_as_uint(bk[nt * 8 + 4 * BS]);
            mma8(acc[nt], a0, a1, a2, a3, b0, b1);
        }
    }
}

template <int NT> __device__ __forceinline__ void zacc(float (&acc)[NT][4]) {
#pragma unroll
    for (int i = 0; i < NT; i++)
#pragma unroll
        for (int j = 0; j < 4; j++) acc[i][j] = 0.f;
}

__global__ void __launch_bounds__(TPB, 2) mlp_fused_kernel(
    const float* __restrict__ feat,   const float* __restrict__ noise,
    const float* __restrict__ Ws0,    const float* __restrict__ bs0,
    const float* __restrict__ Ws1,    const float* __restrict__ bs1,
    const float* __restrict__ Wv,     const float* __restrict__ bv,
    const float* __restrict__ w_gate, const float* __restrict__ w_noise,
    const float* __restrict__ We1,    const float* __restrict__ be1,
    const float* __restrict__ We2,    const float* __restrict__ be2,
    float* __restrict__ out_action, float* __restrict__ out_vf,
    float* __restrict__ out_expout)
{
    extern __shared__ float sm[];
    float* sW   = sm + SW_OFF;    // staged weights (tf32) / later eh
    float* sGB  = sm + SGB_OFF;   // [64][8] packed [w_gate|w_noise]
    float* sG   = sm + SG_OFF;    // gates [128][2]
    float* sAct = sm + SACT_OFF;  // gate*expout [128][12]
    float* sW2  = sm + SW2_OFF;   // We2(768)+be2(12)

    const int tid  = threadIdx.x;
    const int lane = tid & 31;
    const int wrow = (tid >> 5) * 16;
    const int r = lane >> 2, c = lane & 3;
    const int row0 = blockIdx.x * ROWS;

    // ---- stage: Ws0 (tf32, k-major [128][136]), gating B, We2/be2 ----
    for (int i = tid; i < 128 * 32; i += TPB) {
        int k = i >> 5, c4 = (i & 31) << 2;
        float4 v = *(const float4*)&Ws0[k * 128 + c4];
        v.x = tf(v.x); v.y = tf(v.y); v.z = tf(v.z); v.w = tf(v.w);
        *(float4*)&sW[k * SW_S + c4] = v;
    }
    for (int i = tid; i < 512; i += TPB) {
        int k = i >> 3, j = i & 7;
        float v = 0.f;
        if (k < 62) {
            if (j < 2)      v = w_gate[k * 2 + j];
            else if (j < 4) v = w_noise[k * 2 + (j - 2)];
        }
        sGB[i] = tf(v);
    }
    for (int i = tid; i < 768; i += TPB) sW2[i] = We2[i];
    if (tid < 12) sW2[768 + tid] = be2[tid];
    __syncthreads();

    // ================= Phase A: h = tanh(feat @ Ws0 + bs0), N=128 ==========
    float hA[16][4];   // acc -> h frags -> A frags (in place)
    {
        zacc(hA);
        const float* fb  = feat + (size_t)(row0 + wrow + r) * 128 + c;
        const float* fb8 = fb + 8 * 128;
        const float* bw  = sW + c * SW_S + r;
#pragma unroll
        for (int blk = 0; blk < 4; blk++) {
            float f0[4], f1[4], f2v[4], f3[4];
#pragma unroll
            for (int kk = 0; kk < 4; kk++) {
                int kc = blk * 4 + kk;
                f0[kk]  = fb[kc * 8];
                f1[kk]  = fb8[kc * 8];
                f2v[kk] = fb[kc * 8 + 4];
                f3[kk]  = fb8[kc * 8 + 4];
            }
#pragma unroll
            for (int kk = 0; kk < 4; kk++) {
                int kc = blk * 4 + kk;
                unsigned a0 = f2tf_u(f0[kk]), a1 = f2tf_u(f1[kk]);
                unsigned a2 = f2tf_u(f2v[kk]), a3 = f2tf_u(f3[kk]);
                const float* bk = bw + kc * 8 * SW_S;
#pragma unroll
                for (int nt = 0; nt < 16; nt++) {
                    unsigned b0 = __float_as_uint(bk[nt * 8]);
                    unsigned b1 = __float_as_uint(bk[nt * 8 + 4 * SW_S]);
                    mma8(hA[nt], a0, a1, a2, a3, b0, b1);
                }
            }
        }
        // epilogue: tanh + tf32 round + convert output frag -> A frag
#pragma unroll
        for (int nt = 0; nt < 16; nt++) {
            float2 bb = *(const float2*)&bs0[nt * 8 + 2 * c];
            hA[nt][0] = tf(tanh_fast(hA[nt][0] + bb.x));
            hA[nt][1] = tf(tanh_fast(hA[nt][1] + bb.y));
            hA[nt][2] = tf(tanh_fast(hA[nt][2] + bb.x));
            hA[nt][3] = tf(tanh_fast(hA[nt][3] + bb.y));
            frag_to_a(hA[nt], lane);
        }
    }
    __syncthreads();
    // stage Ws1 (tf32, [128][72], cols>=62 zero)
    for (int i = tid; i < 128 * 64; i += TPB) {
        int k = i >> 6, n = i & 63;
        sW[k * SW1_S + n] = (n < 62) ? tf(Ws1[k * 62 + n]) : 0.f;
    }
    __syncthreads();

    // ================= Phase B: latent = tanh(h @ Ws1 + bs1), N=64 =========
    float la[8][4];
    {
        zacc(la);
        mma_panel<16, 8, SW1_S>(sW, hA, la, lane);
#pragma unroll
        for (int nt = 0; nt < 8; nt++) {
            int col = nt * 8 + 2 * c;
            float bx = (col < 62)     ? bs1[col]     : 0.f;
            float by = (col + 1 < 62) ? bs1[col + 1] : 0.f;
            la[nt][0] = tf(tanh_fast(la[nt][0] + bx));
            la[nt][1] = tf(tanh_fast(la[nt][1] + by));
            la[nt][2] = tf(tanh_fast(la[nt][2] + bx));
            la[nt][3] = tf(tanh_fast(la[nt][3] + by));
            frag_to_a(la[nt], lane);
        }
    }

    // ============ Gating via MMA against sGB [64][8] ========================
    {
        float g[1][4];
        zacc(g);
        mma_panel<8, 1, 8>(sGB, la, g, lane);
        int base = lane & ~3;
        float v00 = __shfl_sync(0xffffffffu, g[0][0], base);
        float v01 = __shfl_sync(0xffffffffu, g[0][1], base);
        float v10 = __shfl_sync(0xffffffffu, g[0][0], base + 1);
        float v11 = __shfl_sync(0xffffffffu, g[0][1], base + 1);
        float v20 = __shfl_sync(0xffffffffu, g[0][2], base);
        float v21 = __shfl_sync(0xffffffffu, g[0][3], base);
        float v30 = __shfl_sync(0xffffffffu, g[0][2], base + 1);
        float v31 = __shfl_sync(0xffffffffu, g[0][3], base + 1);
        if (c < 2) {
            float cl0 = (c == 0) ? v00 : v20;
            float cl1 = (c == 0) ? v01 : v21;
            float n0  = (c == 0) ? v10 : v30;
            float n1  = (c == 0) ? v11 : v31;
            int row = wrow + r + ((c == 0) ? 0 : 8);
            float2 nz = *(const float2*)&noise[(size_t)(row0 + row) * 2];
            float s0 = softplus_fast(n0) + 1e-2f;
            float s1 = softplus_fast(n1) + 1e-2f;
            float z0 = fmaf(nz.x, s0, cl0);
            float z1 = fmaf(nz.y, s1, cl1);
            float mx = fmaxf(z0, z1);
            float e0 = __expf(z0 - mx), e1 = __expf(z1 - mx);
            float inv = 1.f / (e0 + e1);
            sG[2 * row + 0] = e0 * inv;
            sG[2 * row + 1] = e1 * inv;
        }
    }
    __syncthreads();
    // stage Wv (tf32, [64][136], rows>=62 zero)
    for (int i = tid; i < 64 * 128; i += TPB) {
        int k = i >> 7, n = i & 127;
        sW[k * SW_S + n] = (k < 62) ? tf(Wv[k * 128 + n]) : 0.f;
    }
    __syncthreads();

    // ============ Phase C: latent_vf = tanh(latent @ Wv + bv), N=128 =======
    {
        float acc[16][4];
        zacc(acc);
        mma_panel<8, 16, SW_S>(sW, la, acc, lane);
#pragma unroll
        for (int nt = 0; nt < 16; nt++) {
            int col = nt * 8 + 2 * c;
            float2 bb = *(const float2*)&bv[col];
            float2 lo, hi;
            lo.x = tanh_fast(acc[nt][0] + bb.x);
            lo.y = tanh_fast(acc[nt][1] + bb.y);
            hi.x = tanh_fast(acc[nt][2] + bb.x);
            hi.y = tanh_fast(acc[nt][3] + bb.y);
            *(float2*)&out_vf[(size_t)(row0 + wrow + r) * 128 + col]     = lo;
            *(float2*)&out_vf[(size_t)(row0 + wrow + r + 8) * 128 + col] = hi;
        }
    }
    __syncthreads();
    // stage We1 concat (tf32, [64][136], cols = e*64+hid, rows>=62 zero)
    for (int i = tid; i < 64 * 128; i += TPB) {
        int k = i >> 7, n = i & 127;
        sW[k * SW_S + n] = (k < 62) ? tf(We1[(((n >> 6) * 62 + k) << 6) + (n & 63)]) : 0.f;
    }
    __syncthreads();

    // ========= Phase E: eh = relu(latent @ We1 + be1), N=128 ===============
    {
        float acc[16][4];
        zacc(acc);
        mma_panel<8, 16, SW_S>(sW, la, acc, lane);
#pragma unroll
        for (int nt = 0; nt < 16; nt++) {
            int col = nt * 8 + 2 * c;
            float2 bb = *(const float2*)&be1[col];
            acc[nt][0] = fmaxf(acc[nt][0] + bb.x, 0.f);
            acc[nt][1] = fmaxf(acc[nt][1] + bb.y, 0.f);
            acc[nt][2] = fmaxf(acc[nt][2] + bb.x, 0.f);
            acc[nt][3] = fmaxf(acc[nt][3] + bb.y, 0.f);
        }
        __syncthreads();   // all warps done reading We1 from sW
#pragma unroll
        for (int nt = 0; nt < 16; nt++) {
            int col = nt * 8 + 2 * c;
            *(float2*)&sW[(wrow + r) * SEH_S + col]     = make_float2(acc[nt][0], acc[nt][1]);
            *(float2*)&sW[(wrow + r + 8) * SEH_S + col] = make_float2(acc[nt][2], acc[nt][3]);
        }
    }
    __syncthreads();

    // ====== Phase F: expert softmax + gated combine (thread=(row,e)) =======
    {
        int row = tid >> 1, e = tid & 1;
        f2 lg[3];
#pragma unroll
        for (int o = 0; o < 3; o++) lg[o].v = *(const float2*)&sW2[768 + e * 6 + 2 * o];
        const float*  ehrow = &sW[row * SEH_S + e * 64];
        const float2* w2    = (const float2*)&sW2[e * 64 * 6];
#pragma unroll 8
        for (int h = 0; h < 64; h++) {
            f2 x = dup2(ehrow[h]);
            f2 w0, w1, w2v;
            w0.v = w2[h * 3 + 0]; w1.v = w2[h * 3 + 1]; w2v.v = w2[h * 3 + 2];
            fma2(lg[0], x, w0);
            fma2(lg[1], x, w1);
            fma2(lg[2], x, w2v);
        }
        float lgs[6] = {lg[0].v.x, lg[0].v.y, lg[1].v.x, lg[1].v.y, lg[2].v.x, lg[2].v.y};
        float m = lgs[0];
#pragma unroll
        for (int o = 1; o < 6; o++) m = fmaxf(m, lgs[o]);
        float p[6], s = 0.f;
#pragma unroll
        for (int o = 0; o < 6; o++) { p[o] = __expf(lgs[o] - m); s += p[o]; }
        float inv = 1.f / s;
        float g = sG[tid];
        size_t gbase = ((size_t)(row0 + row) * 2 + e) * 6;
#pragma unroll
        for (int o = 0; o < 6; o++) {
            float po = p[o] * inv;
            out_expout[gbase + o] = po;
            sAct[tid * 6 + o] = g * po;
        }
    }
    __syncthreads();
    if (tid < 128) {
        size_t gbase = (size_t)(row0 + tid) * 6;
#pragma unroll
        for (int o = 0; o < 6; o++)
            out_action[gbase + o] = sAct[tid * 12 + o] + sAct[tid * 12 + 6 + o];
    }
}

extern "C" void kernel_launch(void* const* d_in, const int* in_sizes, int n_in,
                              void* d_out, int out_size) {
    const float* feat    = (const float*)d_in[0];
    const float* noise   = (const float*)d_in[1];
    const float* Ws0     = (const float*)d_in[2];
    const float* bs0     = (const float*)d_in[3];
    const float* Ws1     = (const float*)d_in[4];
    const float* bs1     = (const float*)d_in[5];
    const float* Wv      = (const float*)d_in[6];
    const float* bv      = (const float*)d_in[7];
    const float* w_gate  = (const float*)d_in[8];
    const float* w_noise = (const float*)d_in[9];
    const float* We1     = (const float*)d_in[10];
    const float* be1     = (const float*)d_in[11];
    const float* We2     = (const float*)d_in[12];
    const float* be2     = (const float*)d_in[13];

    const int B = in_sizes[0] / 128;

    float* out        = (float*)d_out;
    float* out_action = out;                       // [B,6]
    float* out_vf     = out + (size_t)B * 6;       // [B,128]
    float* out_expout = out + (size_t)B * 134;     // [B,2,6]

    cudaFuncSetAttribute(mlp_fused_kernel,
                         cudaFuncAttributeMaxDynamicSharedMemorySize, SMEM_BYTES);

    mlp_fused_kernel<<<B / ROWS, TPB, SMEM_BYTES>>>(
        feat, noise, Ws0, bs0, Ws1, bs1, Wv, bv, w_gate, w_noise,
        We1, be1, We2, be2, out_action, out_vf, out_expout);
}